// round 15
// baseline (speedup 1.0000x reference)
#include <cuda_runtime.h>

#define BB     16
#define TENC   128
#define TDEC   100
#define INDIM  256
#define HID    256
#define OUTD   400
#define MEMD   80
#define BLEN   17
#define BDIM   336
#define BSZ    5712
#define MH1    40
#define U1N    571
#define U1P    576
#define HLEN   117
#define HHL    132        /* reversed hh history length */

#define S1     14         /* u1 k-splits, chunk 384  (5 col-blocks -> 70 CTAs) */
#define C1     384
#define S2     16         /* pq k-splits, chunk 357  (2 col-blocks -> 32 CTAs) */
#define C2     357
#define S3     11         /* out k-splits, chunk 373 (4 col-blocks -> 44 CTAs) */
#define C3     373
#define NU1    S1
#define NPQ    S2
#define NOUT   S3

#define GRID   148
#define BLK    256
#define NTH    (GRID*BLK)

#define XS1    385        /* smem strides, odd mod 32 -> conflict-free over b */
#define XS3    337
#define XS4    577

#define OUTS_ELEMS (BB*TDEC*OUTD)
#define ATT_ELEMS  (BB*TDEC*TENC)

typedef unsigned long long u64;

// ---------------- device scratch (static; no allocations) ----------------
__device__ __align__(16) float g_pa[BB*TENC*HID];
__device__ __align__(16) float g_mh[TDEC*BB*MH1];
__device__ __align__(16) float g_memp[TDEC*BB*MEMD];
__device__ __align__(16) float g_hist[BB*HLEN*BDIM];
__device__ __align__(16) float g_hhr[BB*HHL*HID];
__device__ __align__(16) float g_pqp[NPQ*BB*HID];
__device__ __align__(16) float g_u1p[NU1*BB*U1P];
__device__ __align__(16) float g_outp[16*BB*OUTD];      // also cst staging (16 slices)
__device__ __align__(16) float g_ru1[BB*U1P];
__device__ __align__(16) float g_top[BB*BDIM];
__device__ __align__(16) float g_w1pad[(long)BSZ*U1P];
__device__ __align__(16) float g_W2S[U1N*HID];
__device__ __align__(16) float g_W0[U1N*OUTD];
__device__ __align__(16) float g_b2s[HID];
__device__ __align__(16) float g_cst[OUTD];
__device__ unsigned g_cnt = 0;
__device__ unsigned g_gen = 0;

// ---------------- f32x2 helpers ----------------
__device__ __forceinline__ u64 pk1(float a){
    u64 r; asm("mov.b64 %0, {%1, %1};" : "=l"(r) : "f"(a)); return r;
}
__device__ __forceinline__ u64 pkab(float a, float b){
    u64 r; asm("mov.b64 %0, {%1, %2};" : "=l"(r) : "f"(a), "f"(b)); return r;
}
__device__ __forceinline__ void fma2(u64 &c, u64 a, u64 b){
    asm("fma.rn.f32x2 %0, %1, %2, %0;" : "+l"(c) : "l"(a), "l"(b));
}
__device__ __forceinline__ float2 unpk(u64 v){
    float2 f; asm("mov.b64 {%0, %1}, %2;" : "=f"(f.x), "=f"(f.y) : "l"(v)); return f;
}
__device__ __forceinline__ void zero8(u64 a[4]){ a[0]=a[1]=a[2]=a[3]=0ull; }
__device__ __forceinline__ void bias8(u64 a[4], const float* __restrict__ b){
    a[0]=pkab(b[0],b[1]); a[1]=pkab(b[2],b[3]); a[2]=pkab(b[4],b[5]); a[3]=pkab(b[6],b[7]);
}
__device__ __forceinline__ void unp8(const u64 a[4], float v[8]){
    float2 f;
    f=unpk(a[0]); v[0]=f.x; v[1]=f.y;  f=unpk(a[1]); v[2]=f.x; v[3]=f.y;
    f=unpk(a[2]); v[4]=f.x; v[5]=f.y;  f=unpk(a[3]); v[6]=f.x; v[7]=f.y;
}
__device__ __forceinline__ void store8(float* dst, const u64 a[4]){
    float2* d = (float2*)dst;
    d[0]=unpk(a[0]); d[1]=unpk(a[1]); d[2]=unpk(a[2]); d[3]=unpk(a[3]);
}

// acc[0..7] += sum_k x[k] * W[k*ws + (0..7)]   (W 16B-aligned, ws % 4 == 0)
// x may live in shared memory (inlined -> LDS).
__device__ __forceinline__ void dot8(const float* __restrict__ x,
                                     const float* __restrict__ W,
                                     int ws, int K, u64 a[4]){
    #pragma unroll 4
    for (int k = 0; k < K; k++){
        u64 xx = pk1(x[k]);
        ulonglong2 wA = *reinterpret_cast<const ulonglong2*>(W);
        ulonglong2 wB = *reinterpret_cast<const ulonglong2*>(W + 4);
        W += ws;
        fma2(a[0], xx, wA.x); fma2(a[1], xx, wA.y);
        fma2(a[2], xx, wB.x); fma2(a[3], xx, wB.y);
    }
}

// ---------------- grid barrier: acq/rel atomics, NO L1 flush ----------------
__device__ __forceinline__ void gsync(){
    __syncthreads();
    if (threadIdx.x == 0){
        unsigned gen = g_gen;                  // reloaded after prior asm memory clobbers
        unsigned old;
        asm volatile("atom.acq_rel.gpu.add.u32 %0, [%1], 1;"
                     : "=r"(old) : "l"(&g_cnt) : "memory");
        if (old == (unsigned)(GRID - 1)){
            g_cnt = 0u;                        // ordered before release store below
            asm volatile("st.release.gpu.u32 [%0], %1;"
                         :: "l"(&g_gen), "r"(gen + 1u) : "memory");
        } else {
            unsigned cur;
            do {
                asm volatile("ld.acquire.gpu.u32 %0, [%1];"
                             : "=r"(cur) : "l"(&g_gen) : "memory");
            } while (cur == gen);
        }
    }
    __syncthreads();
}

__device__ __forceinline__ float ftanh(float x){
    float e = __expf(2.f * x);
    return 1.f - __fdividef(2.f, e + 1.f);
}

// =======================================================================
__global__ __launch_bounds__(BLK, 1)
void decoder_persist(const float* __restrict__ inputs,  const float* __restrict__ targets,
                     const float* __restrict__ mp_w1,   const float* __restrict__ mp_b1,
                     const float* __restrict__ mp_w2,   const float* __restrict__ mp_b2,
                     const float* __restrict__ bp_w1,   const float* __restrict__ bp_b1,
                     const float* __restrict__ bp_w2,   const float* __restrict__ bp_b2,
                     const float* __restrict__ att_wq,  const float* __restrict__ att_bq,
                     const float* __restrict__ att_wa,  const float* __restrict__ att_ba,
                     const float* __restrict__ att_v,
                     const float* __restrict__ scale_w, const float* __restrict__ scale_b,
                     const float* __restrict__ out_w,   const float* __restrict__ out_b,
                     float* __restrict__ out, int want_attn)
{
    const int tid = blockIdx.x * BLK + threadIdx.x;
    __shared__ __align__(16) float s_x[16*XS4];          // activation staging (union P1/P3/P4)
    __shared__ __align__(16) float s_part[8][32][8];
    __shared__ float s_pq[HID];
    __shared__ float s_sc[TENC];
    __shared__ float s_red[8];

    // ===================== PC1 =====================
    // pad-copy bp_w1 (5712 x 571) -> (5712 x 576)
    for (long i = tid; i < (long)BSZ*U1P; i += NTH){
        int k = (int)(i / U1P), n = (int)(i - (long)k*U1P);
        g_w1pad[i] = (n < U1N) ? bp_w1[(long)k*U1N + n] : 0.f;
    }
    // zero initial buffer rows (hist slots 100..116)
    for (int i = tid; i < BB*BLEN*BDIM; i += NTH){
        int b = i / (BLEN*BDIM), r = i - b*(BLEN*BDIM);
        g_hist[((long)b*HLEN + TDEC)*BDIM + r] = 0.f;
    }
    // zero hhr slots [116,132)
    for (int i = tid; i < BB*16*HID; i += NTH){
        int b = i / (16*HID), r = i - b*(16*HID);
        g_hhr[((long)b*HHL + 116)*HID + r] = 0.f;
    }
    // pa = inputs @ att_wa + att_ba
    for (int i = tid; i < BB*TENC*(HID/8); i += NTH){
        int row = i >> 5, h0 = (i & 31) << 3;
        u64 a[4]; bias8(a, att_ba + h0);
        dot8(inputs + (long)row*INDIM, att_wa + h0, HID, INDIM, a);
        store8(g_pa + (long)row*HID + h0, a);
    }
    // mh = relu(mem @ mp_w1 + mp_b1)
    for (int i = tid; i < TDEC*BB*5; i += NTH){
        int row = i / 5, n0 = (i - row*5) << 3;
        int tt = row >> 4, b = row & 15;
        u64 a[4]; bias8(a, mp_b1 + n0);
        if (tt > 0) dot8(targets + ((long)b*TDEC + (tt-1))*OUTD, mp_w1 + n0, MH1, OUTD, a);
        float v[8]; unp8(a, v);
        #pragma unroll
        for (int j = 0; j < 8; j++) g_mh[(long)row*MH1 + n0 + j] = fmaxf(v[j], 0.f);
    }
    // W2S[j][h] = sum_d bp_w2[j][d] * scale_w[h][d]
    for (int i = tid; i < U1N*HID; i += NTH){
        int j = i >> 8, h = i & 255;
        const float4* x = reinterpret_cast<const float4*>(bp_w2 + (long)j*BDIM);
        const float4* w = reinterpret_cast<const float4*>(scale_w + (long)h*BDIM);
        float acc = 0.f;
        #pragma unroll 4
        for (int k = 0; k < BDIM/4; k++){
            float4 xa = x[k], wa = w[k];
            acc += xa.x*wa.x + xa.y*wa.y + xa.z*wa.z + xa.w*wa.w;
        }
        g_W2S[(long)j*HID + h] = acc;
    }
    // b2s[h] = sum_d bp_b2[d] * scale_w[h][d]
    for (int h = tid; h < HID; h += NTH){
        const float* w = scale_w + (long)h*BDIM;
        float acc = 0.f;
        for (int k = 0; k < BDIM; k++) acc += bp_b2[k]*w[k];
        g_b2s[h] = acc;
    }
    // cst staging: sum_k scale_b[k%256] * out_w[k][o]  (16 row-slices of 272)
    for (int i = tid; i < 16*50; i += NTH){
        int p = i / 50, o0 = (i - p*50) << 3;
        u64 a[4]; zero8(a);
        const float* W = out_w + (long)(p*272)*OUTD + o0;
        for (int k = 0; k < 272; k++){
            u64 xx = pk1(scale_b[(p*272 + k) & 255]);
            ulonglong2 wA = *reinterpret_cast<const ulonglong2*>(W);
            ulonglong2 wB = *reinterpret_cast<const ulonglong2*>(W + 4);
            W += OUTD;
            fma2(a[0],xx,wA.x); fma2(a[1],xx,wA.y); fma2(a[2],xx,wB.x); fma2(a[3],xx,wB.y);
        }
        store8(g_outp + (long)p*OUTD + o0, a);
    }
    gsync();

    // ===================== PC2 =====================
    // memp = mh @ mp_w2 + mp_b2
    for (int i = tid; i < TDEC*BB*10; i += NTH){
        int row = i / 10, n0 = (i - row*10) << 3;
        u64 a[4]; bias8(a, mp_b2 + n0);
        dot8(g_mh + (long)row*MH1, mp_w2 + n0, MEMD, MH1, a);
        store8(g_memp + (long)row*MEMD + n0, a);
    }
    // W0 = W2S @ out_w[0:256]
    for (int i = tid; i < U1N*50; i += NTH){
        int j = i / 50, o0 = (i - j*50) << 3;
        u64 a[4]; zero8(a);
        dot8(g_W2S + (long)j*HID, out_w + o0, OUTD, HID, a);
        store8(g_W0 + (long)j*OUTD + o0, a);
    }
    // cst = out_b + scale_b-fold + b2s @ out_w[0:256]
    for (int o = tid; o < OUTD; o += NTH){
        float v = out_b[o];
        for (int p = 0; p < 16; p++) v += g_outp[(long)p*OUTD + o];
        for (int h = 0; h < HID; h++) v += g_b2s[h] * out_w[(long)h*OUTD + o];
        g_cst[o] = v;
    }
    gsync();

    // ===================== decode loop =====================
    for (int t = 0; t < TDEC; t++){
        const int hbase = TDEC - t;

        // ---- P1: big GEMM partials (smem-staged x; weights L1-persistent) ----
        {
            const int cb = blockIdx.x;
            const int tj = threadIdx.x >> 4;
            const int b  = threadIdx.x & 15;
            if (cb < 70){                                   // u1 old rows
                int jb = cb / S1, p = cb - jb*S1;
                int j0 = jb*128 + tj*8, k0 = p*C1;
                #pragma unroll
                for (int bb = 0; bb < 16; bb++)
                    for (int kk = threadIdx.x; kk < C1; kk += BLK)
                        s_x[bb*XS1 + kk] = __ldcg(&g_hist[(long)(bb*HLEN + hbase)*BDIM + k0 + kk]);
                __syncthreads();
                if (j0 < U1P){
                    const float* W = g_w1pad + (long)(BDIM + k0)*U1P + j0;
                    u64 a[4]; zero8(a);
                    dot8(s_x + b*XS1, W, U1P, C1, a);
                    store8(g_u1p + (long)(p*BB + b)*U1P + j0, a);
                }
            } else if (cb < 102){                           // pq
                int idx = cb - 70;
                int hb = idx >> 4, p = idx & 15;
                int h0 = hb*128 + tj*8, k0 = p*C2;
                #pragma unroll
                for (int bb = 0; bb < 16; bb++)
                    for (int kk = threadIdx.x; kk < C2; kk += BLK)
                        s_x[bb*XS1 + kk] = __ldcg(&g_hist[(long)(bb*HLEN + hbase)*BDIM + k0 + kk]);
                __syncthreads();
                {
                    const float* W = att_wq + (long)k0*HID + h0;
                    u64 a[4]; zero8(a);
                    dot8(s_x + b*XS1, W, HID, C2, a);
                    store8(g_pqp + (long)(p*BB + b)*HID + h0, a);
                }
            } else if (cb < 146){                           // out FIR l=1..16 (reversed hh)
                int idx = cb - 102;
                int ob = idx / S3, p = idx - ob*S3;
                int o0 = ob*128 + tj*8, k0 = p*C3;
                int kl = min(C3, 4096 - k0);
                #pragma unroll
                for (int bb = 0; bb < 16; bb++)
                    for (int kk = threadIdx.x; kk < kl; kk += BLK)
                        s_x[bb*XS1 + kk] = __ldcg(&g_hhr[(long)(bb*HHL + (116 - t))*HID + k0 + kk]);
                __syncthreads();
                if (o0 < OUTD){
                    const float* W = out_w + (long)(HID + k0)*OUTD + o0;
                    u64 a[4]; zero8(a);
                    dot8(s_x + b*XS1, W, OUTD, kl, a);
                    store8(g_outp + (long)(p*BB + b)*OUTD + o0, a);
                }
            }
        }
        gsync();

        // ---- P2: attention (blocks 0..15) ----
        if (blockIdx.x < BB){
            int b = blockIdx.x, tx = threadIdx.x;
            {   float v = att_bq[tx];
                #pragma unroll
                for (int p = 0; p < NPQ; p++) v += __ldcg(&g_pqp[(long)(p*BB + b)*HID + tx]);
                s_pq[tx] = v;
            }
            __syncthreads();
            int te = tx >> 1, h0 = (tx & 1) << 7;
            float part = 0.f;
            const float* pa = g_pa + ((long)b*TENC + te)*HID + h0;
            const float* av = att_v + h0;
            #pragma unroll 4
            for (int h = 0; h < 128; h++)
                part += ftanh(s_pq[h0 + h] + pa[h]) * av[h];
            part += __shfl_xor_sync(0xffffffffu, part, 1);
            if ((tx & 1) == 0) s_sc[te] = part;
            __syncthreads();
            float m;
            {
                float x = (tx < TENC) ? s_sc[tx] : -1e30f;
                for (int o = 16; o > 0; o >>= 1) x = fmaxf(x, __shfl_xor_sync(~0u, x, o));
                if ((tx & 31) == 0) s_red[tx >> 5] = x;
                __syncthreads();
                m = fmaxf(fmaxf(s_red[0], s_red[1]), fmaxf(s_red[2], s_red[3]));
            }
            float e = (tx < TENC) ? __expf(s_sc[tx] - m) : 0.f;
            float ssum;
            {
                float x = e;
                for (int o = 16; o > 0; o >>= 1) x += __shfl_xor_sync(~0u, x, o);
                __syncthreads();
                if ((tx & 31) == 0) s_red[tx >> 5] = x;
                __syncthreads();
                ssum = s_red[0] + s_red[1] + s_red[2] + s_red[3];
            }
            if (tx < TENC){
                float aw = e / ssum;
                s_sc[tx] = aw;
                if (want_attn)
                    out[OUTS_ELEMS + ((long)b*TDEC + t)*TENC + tx] = aw;
            }
            __syncthreads();
            {   float c = 0.f;
                const float* ip = inputs + (long)b*TENC*INDIM + tx;
                #pragma unroll 4
                for (int k = 0; k < TENC; k++) c += s_sc[k] * ip[(long)k*INDIM];
                g_top[b*BDIM + tx] = c;
            }
            if (tx < MEMD)
                g_top[b*BDIM + INDIM + tx] = g_memp[((long)t*BB + b)*MEMD + tx];
        }
        gsync();

        // ---- P3: u1 finalize over top + relu (36 CTAs, staged top) ----
        if (blockIdx.x < 36){
            #pragma unroll
            for (int bb = 0; bb < 16; bb++)
                for (int kk = threadIdx.x; kk < BDIM; kk += BLK)
                    s_x[bb*XS3 + kk] = __ldcg(&g_top[bb*BDIM + kk]);
            __syncthreads();
            int tj = threadIdx.x >> 4, b = threadIdx.x & 15;
            int j = blockIdx.x*16 + tj;
            int jc = min(j, U1N - 1);
            float acc = bp_b1[jc];
            #pragma unroll
            for (int p = 0; p < NU1; p++) acc += __ldcg(&g_u1p[(long)(p*BB + b)*U1P + j]);
            const float* xs = s_x + b*XS3;
            const float* w = bp_w1 + jc;
            float a0=0.f, a1=0.f, a2=0.f, a3=0.f;
            #pragma unroll 2
            for (int k = 0; k < BDIM; k += 4){
                a0 += xs[k]   * w[(long)k*U1N];
                a1 += xs[k+1] * w[(long)(k+1)*U1N];
                a2 += xs[k+2] * w[(long)(k+2)*U1N];
                a3 += xs[k+3] * w[(long)(k+3)*U1N];
            }
            acc += (a0 + a1) + (a2 + a3);
            if (j < U1N) g_ru1[b*U1P + j] = fmaxf(acc, 0.f);
        }
        gsync();

        // ---- P4: u / hh / out from relu(u1) (62 CTAs, staged ru1) ----
        if (blockIdx.x < 62){
            #pragma unroll
            for (int bb = 0; bb < 16; bb++)
                for (int kk = threadIdx.x; kk < U1N; kk += BLK)
                    s_x[bb*XS4 + kk] = __ldcg(&g_ru1[bb*U1P + kk]);
            __syncthreads();
            const int w   = threadIdx.x >> 5;
            const int og2 = (threadIdx.x >> 4) & 1;
            const int b   = threadIdx.x & 15;
            const int k0  = w * 72;
            const int kl  = min(72, U1N - k0);
            const float* x = s_x + b*XS4 + k0;
            u64 a[4];
            if (blockIdx.x < 21){                           // u
                int c0 = blockIdx.x*16 + og2*8;
                if (w == 0) bias8(a, bp_b2 + c0); else zero8(a);
                dot8(x, bp_w2 + (long)k0*BDIM + c0, BDIM, kl, a);
            } else if (blockIdx.x < 37){                    // hh
                int c0 = (blockIdx.x - 21)*16 + og2*8;
                if (w == 0) bias8(a, g_b2s + c0); else zero8(a);
                dot8(x, g_W2S + (long)k0*HID + c0, HID, kl, a);
            } else {                                        // out finalize
                int c0 = (blockIdx.x - 37)*16 + og2*8;
                float s[8];
                float4 pA = __ldcg(reinterpret_cast<const float4*>(&g_outp[(long)(w*BB + b)*OUTD + c0]));
                float4 pB = __ldcg(reinterpret_cast<const float4*>(&g_outp[(long)(w*BB + b)*OUTD + c0 + 4]));
                s[0]=pA.x; s[1]=pA.y; s[2]=pA.z; s[3]=pA.w;
                s[4]=pB.x; s[5]=pB.y; s[6]=pB.z; s[7]=pB.w;
                if (w == 0){
                    #pragma unroll
                    for (int i = 0; i < 8; i++) s[i] += g_cst[c0 + i];
                }
                if (w < 3){
                    float4 qA = __ldcg(reinterpret_cast<const float4*>(&g_outp[(long)((w+8)*BB + b)*OUTD + c0]));
                    float4 qB = __ldcg(reinterpret_cast<const float4*>(&g_outp[(long)((w+8)*BB + b)*OUTD + c0 + 4]));
                    s[0]+=qA.x; s[1]+=qA.y; s[2]+=qA.z; s[3]+=qA.w;
                    s[4]+=qB.x; s[5]+=qB.y; s[6]+=qB.z; s[7]+=qB.w;
                }
                a[0]=pkab(s[0],s[1]); a[1]=pkab(s[2],s[3]);
                a[2]=pkab(s[4],s[5]); a[3]=pkab(s[6],s[7]);
                dot8(x, g_W0 + (long)k0*OUTD + c0, OUTD, kl, a);
            }
            store8(&s_part[w][og2*16 + b][0], a);
            __syncthreads();
            {
                int oi = threadIdx.x, gb = oi >> 3, c = oi & 7;
                float v = 0.f;
                #pragma unroll
                for (int ww = 0; ww < 8; ww++) v += s_part[ww][gb][c];
                int b2 = gb & 15, og = gb >> 4;
                int col = ((blockIdx.x < 21) ? blockIdx.x*16
                         : (blockIdx.x < 37) ? (blockIdx.x-21)*16
                                             : (blockIdx.x-37)*16) + og*8 + c;
                if (blockIdx.x < 21)
                    g_hist[(long)(b2*HLEN + (TDEC-1 - t))*BDIM + col] = v;
                else if (blockIdx.x < 37)
                    g_hhr[(long)(b2*HHL + (115 - t))*HID + col] = v;
                else
                    out[((long)b2*TDEC + t)*OUTD + col] = v;
            }
        }
        gsync();
    }
}

extern "C" void kernel_launch(void* const* d_in, const int* in_sizes, int n_in,
                              void* d_out, int out_size) {
    (void)in_sizes; (void)n_in;
    int want_attn = (out_size >= OUTS_ELEMS + ATT_ELEMS) ? 1 : 0;
    decoder_persist<<<GRID, BLK>>>(
        (const float*)d_in[0],  (const float*)d_in[1],
        (const float*)d_in[2],  (const float*)d_in[3],
        (const float*)d_in[4],  (const float*)d_in[5],
        (const float*)d_in[6],  (const float*)d_in[7],
        (const float*)d_in[8],  (const float*)d_in[9],
        (const float*)d_in[10], (const float*)d_in[11],
        (const float*)d_in[12], (const float*)d_in[13],
        (const float*)d_in[14],
        (const float*)d_in[15], (const float*)d_in[16],
        (const float*)d_in[17], (const float*)d_in[18],
        (float*)d_out, want_attn);
}

// round 16
// speedup vs baseline: 1.1691x; 1.1691x over previous
#include <cuda_runtime.h>

#define BB     16
#define TENC   128
#define TDEC   100
#define INDIM  256
#define HID    256
#define OUTD   400
#define MEMD   80
#define BLEN   17
#define BDIM   336
#define BSZ    5712
#define MH1    40
#define U1N    571
#define U1P    576
#define HLEN   117
#define HHL    132        /* reversed hh history length */

#define S1     14         /* u1 k-splits, chunk 384  (5 col-blocks -> 70 CTAs) */
#define C1     384
#define S2     16         /* pq k-splits, chunk 357  (2 col-blocks -> 32 CTAs) */
#define C2     357
#define S3     11         /* out k-splits, chunk 373 (4 col-blocks -> 44 CTAs) */
#define C3     373
#define NU1    S1
#define NPQ    S2
#define NOUT   S3

#define GRID   148
#define BLK    256
#define NTH    (GRID*BLK)

#define XS1    385        /* smem strides, odd mod 32 -> conflict-free over b */
#define XS3    337
#define XS4    577

#define OUTS_ELEMS (BB*TDEC*OUTD)
#define ATT_ELEMS  (BB*TDEC*TENC)

typedef unsigned long long u64;

// ---------------- device scratch (static; no allocations) ----------------
__device__ __align__(16) float g_pa[BB*TENC*HID];
__device__ __align__(16) float g_mh[TDEC*BB*MH1];
__device__ __align__(16) float g_memp[TDEC*BB*MEMD];
__device__ __align__(16) float g_hist[BB*HLEN*BDIM];
__device__ __align__(16) float g_hhr[BB*HHL*HID];
__device__ __align__(16) float g_pqp[NPQ*BB*HID];
__device__ __align__(16) float g_u1p[NU1*BB*U1P];
__device__ __align__(16) float g_outp[16*BB*OUTD];      // also cst staging (16 slices)
__device__ __align__(16) float g_ru1[BB*U1P];
__device__ __align__(16) float g_top[BB*BDIM];
__device__ __align__(16) float g_w1pad[(long)BSZ*U1P];
__device__ __align__(16) float g_W2S[U1N*HID];
__device__ __align__(16) float g_W0[U1N*OUTD];
__device__ __align__(16) float g_b2s[HID];
__device__ __align__(16) float g_cst[OUTD];
__device__ unsigned g_cnt = 0;
__device__ unsigned g_gen = 0;

// ---------------- f32x2 helpers ----------------
__device__ __forceinline__ u64 pk1(float a){
    u64 r; asm("mov.b64 %0, {%1, %1};" : "=l"(r) : "f"(a)); return r;
}
__device__ __forceinline__ u64 pkab(float a, float b){
    u64 r; asm("mov.b64 %0, {%1, %2};" : "=l"(r) : "f"(a), "f"(b)); return r;
}
__device__ __forceinline__ void fma2(u64 &c, u64 a, u64 b){
    asm("fma.rn.f32x2 %0, %1, %2, %0;" : "+l"(c) : "l"(a), "l"(b));
}
__device__ __forceinline__ float2 unpk(u64 v){
    float2 f; asm("mov.b64 {%0, %1}, %2;" : "=f"(f.x), "=f"(f.y) : "l"(v)); return f;
}
__device__ __forceinline__ void zero8(u64 a[4]){ a[0]=a[1]=a[2]=a[3]=0ull; }
__device__ __forceinline__ void bias8(u64 a[4], const float* __restrict__ b){
    a[0]=pkab(b[0],b[1]); a[1]=pkab(b[2],b[3]); a[2]=pkab(b[4],b[5]); a[3]=pkab(b[6],b[7]);
}
__device__ __forceinline__ void unp8(const u64 a[4], float v[8]){
    float2 f;
    f=unpk(a[0]); v[0]=f.x; v[1]=f.y;  f=unpk(a[1]); v[2]=f.x; v[3]=f.y;
    f=unpk(a[2]); v[4]=f.x; v[5]=f.y;  f=unpk(a[3]); v[6]=f.x; v[7]=f.y;
}
__device__ __forceinline__ void store8(float* dst, const u64 a[4]){
    float2* d = (float2*)dst;
    d[0]=unpk(a[0]); d[1]=unpk(a[1]); d[2]=unpk(a[2]); d[3]=unpk(a[3]);
}

// acc[0..7] += sum_k x[k] * W[k*ws + (0..7)]   (W 16B-aligned, ws % 4 == 0)
// x may live in shared memory (inlined -> LDS). High unroll -> deep LDG batching.
__device__ __forceinline__ void dot8(const float* __restrict__ x,
                                     const float* __restrict__ W,
                                     int ws, int K, u64 a[4]){
    #pragma unroll 16
    for (int k = 0; k < K; k++){
        u64 xx = pk1(x[k]);
        ulonglong2 wA = *reinterpret_cast<const ulonglong2*>(W);
        ulonglong2 wB = *reinterpret_cast<const ulonglong2*>(W + 4);
        W += ws;
        fma2(a[0], xx, wA.x); fma2(a[1], xx, wA.y);
        fma2(a[2], xx, wB.x); fma2(a[3], xx, wB.y);
    }
}

// ---------------- grid barrier: acq/rel atomics, NO L1 flush ----------------
__device__ __forceinline__ void gsync(){
    __syncthreads();
    if (threadIdx.x == 0){
        unsigned gen = g_gen;                  // reloaded after prior asm memory clobbers
        unsigned old;
        asm volatile("atom.acq_rel.gpu.add.u32 %0, [%1], 1;"
                     : "=r"(old) : "l"(&g_cnt) : "memory");
        if (old == (unsigned)(GRID - 1)){
            g_cnt = 0u;                        // ordered before release store below
            asm volatile("st.release.gpu.u32 [%0], %1;"
                         :: "l"(&g_gen), "r"(gen + 1u) : "memory");
        } else {
            unsigned cur;
            do {
                asm volatile("ld.acquire.gpu.u32 %0, [%1];"
                             : "=r"(cur) : "l"(&g_gen) : "memory");
            } while (cur == gen);
        }
    }
    __syncthreads();
}

// hardware tanh (MUFU.TANH, sm_75+): 1 MUFU op, ~2^-11 accuracy
__device__ __forceinline__ float ftanh(float x){
    float r; asm("tanh.approx.f32 %0, %1;" : "=f"(r) : "f"(x)); return r;
}

// =======================================================================
__global__ __launch_bounds__(BLK, 1)
void decoder_persist(const float* __restrict__ inputs,  const float* __restrict__ targets,
                     const float* __restrict__ mp_w1,   const float* __restrict__ mp_b1,
                     const float* __restrict__ mp_w2,   const float* __restrict__ mp_b2,
                     const float* __restrict__ bp_w1,   const float* __restrict__ bp_b1,
                     const float* __restrict__ bp_w2,   const float* __restrict__ bp_b2,
                     const float* __restrict__ att_wq,  const float* __restrict__ att_bq,
                     const float* __restrict__ att_wa,  const float* __restrict__ att_ba,
                     const float* __restrict__ att_v,
                     const float* __restrict__ scale_w, const float* __restrict__ scale_b,
                     const float* __restrict__ out_w,   const float* __restrict__ out_b,
                     float* __restrict__ out, int want_attn)
{
    const int tid = blockIdx.x * BLK + threadIdx.x;
    __shared__ __align__(16) float s_x[16*XS4];          // activation staging (union P1/P3/P4)
    __shared__ __align__(16) float s_part[8][32][8];
    __shared__ float s_pq[HID];
    __shared__ float s_sc[TENC];
    __shared__ float s_red[8];

    // ===================== PC1 =====================
    // pad-copy bp_w1 (5712 x 571) -> (5712 x 576)
    for (long i = tid; i < (long)BSZ*U1P; i += NTH){
        int k = (int)(i / U1P), n = (int)(i - (long)k*U1P);
        g_w1pad[i] = (n < U1N) ? bp_w1[(long)k*U1N + n] : 0.f;
    }
    // zero initial buffer rows (hist slots 100..116)
    for (int i = tid; i < BB*BLEN*BDIM; i += NTH){
        int b = i / (BLEN*BDIM), r = i - b*(BLEN*BDIM);
        g_hist[((long)b*HLEN + TDEC)*BDIM + r] = 0.f;
    }
    // zero hhr slots [116,132)
    for (int i = tid; i < BB*16*HID; i += NTH){
        int b = i / (16*HID), r = i - b*(16*HID);
        g_hhr[((long)b*HHL + 116)*HID + r] = 0.f;
    }
    // pa = inputs @ att_wa + att_ba
    for (int i = tid; i < BB*TENC*(HID/8); i += NTH){
        int row = i >> 5, h0 = (i & 31) << 3;
        u64 a[4]; bias8(a, att_ba + h0);
        dot8(inputs + (long)row*INDIM, att_wa + h0, HID, INDIM, a);
        store8(g_pa + (long)row*HID + h0, a);
    }
    // mh = relu(mem @ mp_w1 + mp_b1)
    for (int i = tid; i < TDEC*BB*5; i += NTH){
        int row = i / 5, n0 = (i - row*5) << 3;
        int tt = row >> 4, b = row & 15;
        u64 a[4]; bias8(a, mp_b1 + n0);
        if (tt > 0) dot8(targets + ((long)b*TDEC + (tt-1))*OUTD, mp_w1 + n0, MH1, OUTD, a);
        float v[8]; unp8(a, v);
        #pragma unroll
        for (int j = 0; j < 8; j++) g_mh[(long)row*MH1 + n0 + j] = fmaxf(v[j], 0.f);
    }
    // W2S[j][h] = sum_d bp_w2[j][d] * scale_w[h][d]
    for (int i = tid; i < U1N*HID; i += NTH){
        int j = i >> 8, h = i & 255;
        const float4* x = reinterpret_cast<const float4*>(bp_w2 + (long)j*BDIM);
        const float4* w = reinterpret_cast<const float4*>(scale_w + (long)h*BDIM);
        float acc = 0.f;
        #pragma unroll 4
        for (int k = 0; k < BDIM/4; k++){
            float4 xa = x[k], wa = w[k];
            acc += xa.x*wa.x + xa.y*wa.y + xa.z*wa.z + xa.w*wa.w;
        }
        g_W2S[(long)j*HID + h] = acc;
    }
    // b2s[h] = sum_d bp_b2[d] * scale_w[h][d]
    for (int h = tid; h < HID; h += NTH){
        const float* w = scale_w + (long)h*BDIM;
        float acc = 0.f;
        for (int k = 0; k < BDIM; k++) acc += bp_b2[k]*w[k];
        g_b2s[h] = acc;
    }
    // cst staging: sum_k scale_b[k%256] * out_w[k][o]  (16 row-slices of 272)
    for (int i = tid; i < 16*50; i += NTH){
        int p = i / 50, o0 = (i - p*50) << 3;
        u64 a[4]; zero8(a);
        const float* W = out_w + (long)(p*272)*OUTD + o0;
        for (int k = 0; k < 272; k++){
            u64 xx = pk1(scale_b[(p*272 + k) & 255]);
            ulonglong2 wA = *reinterpret_cast<const ulonglong2*>(W);
            ulonglong2 wB = *reinterpret_cast<const ulonglong2*>(W + 4);
            W += OUTD;
            fma2(a[0],xx,wA.x); fma2(a[1],xx,wA.y); fma2(a[2],xx,wB.x); fma2(a[3],xx,wB.y);
        }
        store8(g_outp + (long)p*OUTD + o0, a);
    }
    gsync();

    // ===================== PC2 =====================
    // memp = mh @ mp_w2 + mp_b2
    for (int i = tid; i < TDEC*BB*10; i += NTH){
        int row = i / 10, n0 = (i - row*10) << 3;
        u64 a[4]; bias8(a, mp_b2 + n0);
        dot8(g_mh + (long)row*MH1, mp_w2 + n0, MEMD, MH1, a);
        store8(g_memp + (long)row*MEMD + n0, a);
    }
    // W0 = W2S @ out_w[0:256]
    for (int i = tid; i < U1N*50; i += NTH){
        int j = i / 50, o0 = (i - j*50) << 3;
        u64 a[4]; zero8(a);
        dot8(g_W2S + (long)j*HID, out_w + o0, OUTD, HID, a);
        store8(g_W0 + (long)j*OUTD + o0, a);
    }
    // cst = out_b + scale_b-fold + b2s @ out_w[0:256]
    for (int o = tid; o < OUTD; o += NTH){
        float v = out_b[o];
        for (int p = 0; p < 16; p++) v += g_outp[(long)p*OUTD + o];
        for (int h = 0; h < HID; h++) v += g_b2s[h] * out_w[(long)h*OUTD + o];
        g_cst[o] = v;
    }
    gsync();

    // ===================== decode loop =====================
    for (int t = 0; t < TDEC; t++){
        const int hbase = TDEC - t;

        // ---- P1: big GEMM partials (smem-staged x; deep-MLP weight loads) ----
        {
            const int cb = blockIdx.x;
            const int tj = threadIdx.x >> 4;
            const int b  = threadIdx.x & 15;
            if (cb < 70){                                   // u1 old rows
                int jb = cb / S1, p = cb - jb*S1;
                int j0 = jb*128 + tj*8, k0 = p*C1;
                #pragma unroll
                for (int bb = 0; bb < 16; bb++)
                    for (int kk = threadIdx.x; kk < C1; kk += BLK)
                        s_x[bb*XS1 + kk] = __ldcg(&g_hist[(long)(bb*HLEN + hbase)*BDIM + k0 + kk]);
                __syncthreads();
                if (j0 < U1P){
                    const float* W = g_w1pad + (long)(BDIM + k0)*U1P + j0;
                    u64 a[4]; zero8(a);
                    dot8(s_x + b*XS1, W, U1P, C1, a);
                    store8(g_u1p + (long)(p*BB + b)*U1P + j0, a);
                }
            } else if (cb < 102){                           // pq
                int idx = cb - 70;
                int hb = idx >> 4, p = idx & 15;
                int h0 = hb*128 + tj*8, k0 = p*C2;
                #pragma unroll
                for (int bb = 0; bb < 16; bb++)
                    for (int kk = threadIdx.x; kk < C2; kk += BLK)
                        s_x[bb*XS1 + kk] = __ldcg(&g_hist[(long)(bb*HLEN + hbase)*BDIM + k0 + kk]);
                __syncthreads();
                {
                    const float* W = att_wq + (long)k0*HID + h0;
                    u64 a[4]; zero8(a);
                    dot8(s_x + b*XS1, W, HID, C2, a);
                    store8(g_pqp + (long)(p*BB + b)*HID + h0, a);
                }
            } else if (cb < 146){                           // out FIR l=1..16 (reversed hh)
                int idx = cb - 102;
                int ob = idx / S3, p = idx - ob*S3;
                int o0 = ob*128 + tj*8, k0 = p*C3;
                int kl = min(C3, 4096 - k0);
                #pragma unroll
                for (int bb = 0; bb < 16; bb++)
                    for (int kk = threadIdx.x; kk < kl; kk += BLK)
                        s_x[bb*XS1 + kk] = __ldcg(&g_hhr[(long)(bb*HHL + (116 - t))*HID + k0 + kk]);
                __syncthreads();
                if (o0 < OUTD){
                    const float* W = out_w + (long)(HID + k0)*OUTD + o0;
                    u64 a[4]; zero8(a);
                    dot8(s_x + b*XS1, W, OUTD, kl, a);
                    store8(g_outp + (long)(p*BB + b)*OUTD + o0, a);
                }
            }
        }
        gsync();

        // ---- P2: attention (blocks 0..15) ----
        if (blockIdx.x < BB){
            int b = blockIdx.x, tx = threadIdx.x;
            {   float v = att_bq[tx];
                #pragma unroll
                for (int p = 0; p < NPQ; p++) v += __ldcg(&g_pqp[(long)(p*BB + b)*HID + tx]);
                s_pq[tx] = v;
            }
            __syncthreads();
            int te = tx >> 1, h0 = (tx & 1) << 7;
            float part = 0.f;
            const float* pa = g_pa + ((long)b*TENC + te)*HID + h0;
            const float* av = att_v + h0;
            #pragma unroll 8
            for (int h = 0; h < 128; h++)
                part += ftanh(s_pq[h0 + h] + pa[h]) * av[h];
            part += __shfl_xor_sync(0xffffffffu, part, 1);
            if ((tx & 1) == 0) s_sc[te] = part;
            __syncthreads();
            float m;
            {
                float x = (tx < TENC) ? s_sc[tx] : -1e30f;
                for (int o = 16; o > 0; o >>= 1) x = fmaxf(x, __shfl_xor_sync(~0u, x, o));
                if ((tx & 31) == 0) s_red[tx >> 5] = x;
                __syncthreads();
                m = fmaxf(fmaxf(s_red[0], s_red[1]), fmaxf(s_red[2], s_red[3]));
            }
            float e = (tx < TENC) ? __expf(s_sc[tx] - m) : 0.f;
            float ssum;
            {
                float x = e;
                for (int o = 16; o > 0; o >>= 1) x += __shfl_xor_sync(~0u, x, o);
                __syncthreads();
                if ((tx & 31) == 0) s_red[tx >> 5] = x;
                __syncthreads();
                ssum = s_red[0] + s_red[1] + s_red[2] + s_red[3];
            }
            if (tx < TENC){
                float aw = e / ssum;
                s_sc[tx] = aw;
                if (want_attn)
                    out[OUTS_ELEMS + ((long)b*TDEC + t)*TENC + tx] = aw;
            }
            __syncthreads();
            {   float c = 0.f;
                const float* ip = inputs + (long)b*TENC*INDIM + tx;
                #pragma unroll 8
                for (int k = 0; k < TENC; k++) c += s_sc[k] * ip[(long)k*INDIM];
                g_top[b*BDIM + tx] = c;
            }
            if (tx < MEMD)
                g_top[b*BDIM + INDIM + tx] = g_memp[((long)t*BB + b)*MEMD + tx];
        }
        gsync();

        // ---- P3: u1 finalize over top + relu (36 CTAs, staged top) ----
        if (blockIdx.x < 36){
            #pragma unroll
            for (int bb = 0; bb < 16; bb++)
                for (int kk = threadIdx.x; kk < BDIM; kk += BLK)
                    s_x[bb*XS3 + kk] = __ldcg(&g_top[bb*BDIM + kk]);
            __syncthreads();
            int tj = threadIdx.x >> 4, b = threadIdx.x & 15;
            int j = blockIdx.x*16 + tj;
            int jc = min(j, U1N - 1);
            float acc = bp_b1[jc];
            #pragma unroll
            for (int p = 0; p < NU1; p++) acc += __ldcg(&g_u1p[(long)(p*BB + b)*U1P + j]);
            const float* xs = s_x + b*XS3;
            const float* w = bp_w1 + jc;
            float a0=0.f, a1=0.f, a2=0.f, a3=0.f;
            #pragma unroll 8
            for (int k = 0; k < BDIM; k += 4){
                a0 += xs[k]   * w[(long)k*U1N];
                a1 += xs[k+1] * w[(long)(k+1)*U1N];
                a2 += xs[k+2] * w[(long)(k+2)*U1N];
                a3 += xs[k+3] * w[(long)(k+3)*U1N];
            }
            acc += (a0 + a1) + (a2 + a3);
            if (j < U1N) g_ru1[b*U1P + j] = fmaxf(acc, 0.f);
        }
        gsync();

        // ---- P4: u / hh / out from relu(u1) (62 CTAs, staged ru1) ----
        if (blockIdx.x < 62){
            #pragma unroll
            for (int bb = 0; bb < 16; bb++)
                for (int kk = threadIdx.x; kk < U1N; kk += BLK)
                    s_x[bb*XS4 + kk] = __ldcg(&g_ru1[bb*U1P + kk]);
            __syncthreads();
            const int w   = threadIdx.x >> 5;
            const int og2 = (threadIdx.x >> 4) & 1;
            const int b   = threadIdx.x & 15;
            const int k0  = w * 72;
            const int kl  = min(72, U1N - k0);
            const float* x = s_x + b*XS4 + k0;
            u64 a[4];
            if (blockIdx.x < 21){                           // u
                int c0 = blockIdx.x*16 + og2*8;
                if (w == 0) bias8(a, bp_b2 + c0); else zero8(a);
                dot8(x, bp_w2 + (long)k0*BDIM + c0, BDIM, kl, a);
            } else if (blockIdx.x < 37){                    // hh
                int c0 = (blockIdx.x - 21)*16 + og2*8;
                if (w == 0) bias8(a, g_b2s + c0); else zero8(a);
                dot8(x, g_W2S + (long)k0*HID + c0, HID, kl, a);
            } else {                                        // out finalize
                int c0 = (blockIdx.x - 37)*16 + og2*8;
                float s[8];
                float4 pA = __ldcg(reinterpret_cast<const float4*>(&g_outp[(long)(w*BB + b)*OUTD + c0]));
                float4 pB = __ldcg(reinterpret_cast<const float4*>(&g_outp[(long)(w*BB + b)*OUTD + c0 + 4]));
                s[0]=pA.x; s[1]=pA.y; s[2]=pA.z; s[3]=pA.w;
                s[4]=pB.x; s[5]=pB.y; s[6]=pB.z; s[7]=pB.w;
                if (w == 0){
                    #pragma unroll
                    for (int i = 0; i < 8; i++) s[i] += g_cst[c0 + i];
                }
                if (w < 3){
                    float4 qA = __ldcg(reinterpret_cast<const float4*>(&g_outp[(long)((w+8)*BB + b)*OUTD + c0]));
                    float4 qB = __ldcg(reinterpret_cast<const float4*>(&g_outp[(long)((w+8)*BB + b)*OUTD + c0 + 4]));
                    s[0]+=qA.x; s[1]+=qA.y; s[2]+=qA.z; s[3]+=qA.w;
                    s[4]+=qB.x; s[5]+=qB.y; s[6]+=qB.z; s[7]+=qB.w;
                }
                a[0]=pkab(s[0],s[1]); a[1]=pkab(s[2],s[3]);
                a[2]=pkab(s[4],s[5]); a[3]=pkab(s[6],s[7]);
                dot8(x, g_W0 + (long)k0*OUTD + c0, OUTD, kl, a);
            }
            store8(&s_part[w][og2*16 + b][0], a);
            __syncthreads();
            {
                int oi = threadIdx.x, gb = oi >> 3, c = oi & 7;
                float v = 0.f;
                #pragma unroll
                for (int ww = 0; ww < 8; ww++) v += s_part[ww][gb][c];
                int b2 = gb & 15, og = gb >> 4;
                int col = ((blockIdx.x < 21) ? blockIdx.x*16
                         : (blockIdx.x < 37) ? (blockIdx.x-21)*16
                                             : (blockIdx.x-37)*16) + og*8 + c;
                if (blockIdx.x < 21)
                    g_hist[(long)(b2*HLEN + (TDEC-1 - t))*BDIM + col] = v;
                else if (blockIdx.x < 37)
                    g_hhr[(long)(b2*HHL + (115 - t))*HID + col] = v;
                else
                    out[((long)b2*TDEC + t)*OUTD + col] = v;
            }
        }
        gsync();
    }
}

extern "C" void kernel_launch(void* const* d_in, const int* in_sizes, int n_in,
                              void* d_out, int out_size) {
    (void)in_sizes; (void)n_in;
    int want_attn = (out_size >= OUTS_ELEMS + ATT_ELEMS) ? 1 : 0;
    decoder_persist<<<GRID, BLK>>>(
        (const float*)d_in[0],  (const float*)d_in[1],
        (const float*)d_in[2],  (const float*)d_in[3],
        (const float*)d_in[4],  (const float*)d_in[5],
        (const float*)d_in[6],  (const float*)d_in[7],
        (const float*)d_in[8],  (const float*)d_in[9],
        (const float*)d_in[10], (const float*)d_in[11],
        (const float*)d_in[12], (const float*)d_in[13],
        (const float*)d_in[14],
        (const float*)d_in[15], (const float*)d_in[16],
        (const float*)d_in[17], (const float*)d_in[18],
        (float*)d_out, want_attn);
}

// round 17
// speedup vs baseline: 1.4073x; 1.2037x over previous
#include <cuda_runtime.h>

#define BB     16
#define TENC   128
#define TDEC   100
#define INDIM  256
#define HID    256
#define OUTD   400
#define MEMD   80
#define BLEN   17
#define BDIM   336
#define BSZ    5712
#define MH1    40
#define U1N    571
#define U1P    576
#define HLEN   117
#define HHL    132        /* reversed hh history length */

/* P1 tiling: tiles of 256 threads (16 tj x 16 b) */
#define S1     42         /* u1: 42 k-splits, chunk 128  (5 col-blocks -> 210 tiles) */
#define C1     128
#define S2     42         /* pq: 42 k-splits, chunk 136  (2 col-blocks -> 84 tiles)  */
#define C2     136
#define S3     32         /* out: 32 k-splits, chunk 128 (4 col-blocks -> 128 tiles) */
#define C3     128
#define NU1    S1
#define NPQ    S2
#define NOUT   S3
#define NTILE  422        /* 210 + 84 + 128 */

#define GRID   148
#define BLK    768
#define NTH    (GRID*BLK)

#define GST    2192       /* P1 per-group smem stride: 16 x 137 */
#define SXF    9232       /* s_x floats: 16 x 577 (P4) >= P1 3x2192, P3 16x337 */
#define SMEM_FLOATS (SXF + 6144)   /* + s_part 24x32x8 */

#define OUTS_ELEMS (BB*TDEC*OUTD)
#define ATT_ELEMS  (BB*TDEC*TENC)

typedef unsigned long long u64;

// ---------------- device scratch (static; no allocations) ----------------
__device__ __align__(16) float g_pa[BB*TENC*HID];
__device__ __align__(16) float g_mh[TDEC*BB*MH1];
__device__ __align__(16) float g_memp[TDEC*BB*MEMD];
__device__ __align__(16) float g_hist[BB*HLEN*BDIM];
__device__ __align__(16) float g_hhr[BB*HHL*HID];
__device__ __align__(16) float g_pqp[NPQ*BB*HID];
__device__ __align__(16) float g_u1p[NU1*BB*U1P];
__device__ __align__(16) float g_outp[NOUT*BB*OUTD];    // also cst staging (16 slices)
__device__ __align__(16) float g_ru1[BB*U1P];
__device__ __align__(16) float g_top[BB*BDIM];
__device__ __align__(16) float g_w1pad[(long)BSZ*U1P];
__device__ __align__(16) float g_W2S[U1N*HID];
__device__ __align__(16) float g_W0[U1N*OUTD];
__device__ __align__(16) float g_b2s[HID];
__device__ __align__(16) float g_cst[OUTD];
__device__ unsigned g_cnt = 0;
__device__ unsigned g_gen = 0;

// ---------------- f32x2 helpers ----------------
__device__ __forceinline__ u64 pk1(float a){
    u64 r; asm("mov.b64 %0, {%1, %1};" : "=l"(r) : "f"(a)); return r;
}
__device__ __forceinline__ u64 pkab(float a, float b){
    u64 r; asm("mov.b64 %0, {%1, %2};" : "=l"(r) : "f"(a), "f"(b)); return r;
}
__device__ __forceinline__ void fma2(u64 &c, u64 a, u64 b){
    asm("fma.rn.f32x2 %0, %1, %2, %0;" : "+l"(c) : "l"(a), "l"(b));
}
__device__ __forceinline__ float2 unpk(u64 v){
    float2 f; asm("mov.b64 {%0, %1}, %2;" : "=f"(f.x), "=f"(f.y) : "l"(v)); return f;
}
__device__ __forceinline__ void zero8(u64 a[4]){ a[0]=a[1]=a[2]=a[3]=0ull; }
__device__ __forceinline__ void bias8(u64 a[4], const float* __restrict__ b){
    a[0]=pkab(b[0],b[1]); a[1]=pkab(b[2],b[3]); a[2]=pkab(b[4],b[5]); a[3]=pkab(b[6],b[7]);
}
__device__ __forceinline__ void unp8(const u64 a[4], float v[8]){
    float2 f;
    f=unpk(a[0]); v[0]=f.x; v[1]=f.y;  f=unpk(a[1]); v[2]=f.x; v[3]=f.y;
    f=unpk(a[2]); v[4]=f.x; v[5]=f.y;  f=unpk(a[3]); v[6]=f.x; v[7]=f.y;
}
__device__ __forceinline__ void store8(float* dst, const u64 a[4]){
    float2* d = (float2*)dst;
    d[0]=unpk(a[0]); d[1]=unpk(a[1]); d[2]=unpk(a[2]); d[3]=unpk(a[3]);
}

// acc[0..7] += sum_k x[k] * W[k*ws + (0..7)]   (W 16B-aligned, ws % 4 == 0)
__device__ __forceinline__ void dot8(const float* __restrict__ x,
                                     const float* __restrict__ W,
                                     int ws, int K, u64 a[4]){
    #pragma unroll 8
    for (int k = 0; k < K; k++){
        u64 xx = pk1(x[k]);
        ulonglong2 wA = *reinterpret_cast<const ulonglong2*>(W);
        ulonglong2 wB = *reinterpret_cast<const ulonglong2*>(W + 4);
        W += ws;
        fma2(a[0], xx, wA.x); fma2(a[1], xx, wA.y);
        fma2(a[2], xx, wB.x); fma2(a[3], xx, wB.y);
    }
}

// ---------------- grid barrier: acq/rel atomics, NO L1 flush ----------------
__device__ __forceinline__ void gsync(){
    __syncthreads();
    if (threadIdx.x == 0){
        unsigned gen = g_gen;
        unsigned old;
        asm volatile("atom.acq_rel.gpu.add.u32 %0, [%1], 1;"
                     : "=r"(old) : "l"(&g_cnt) : "memory");
        if (old == (unsigned)(GRID - 1)){
            g_cnt = 0u;
            asm volatile("st.release.gpu.u32 [%0], %1;"
                         :: "l"(&g_gen), "r"(gen + 1u) : "memory");
        } else {
            unsigned cur;
            do {
                asm volatile("ld.acquire.gpu.u32 %0, [%1];"
                             : "=r"(cur) : "l"(&g_gen) : "memory");
            } while (cur == gen);
        }
    }
    __syncthreads();
}

// hardware tanh (MUFU.TANH)
__device__ __forceinline__ float ftanh(float x){
    float r; asm("tanh.approx.f32 %0, %1;" : "=f"(r) : "f"(x)); return r;
}

// =======================================================================
__global__ __launch_bounds__(BLK, 1)
void decoder_persist(const float* __restrict__ inputs,  const float* __restrict__ targets,
                     const float* __restrict__ mp_w1,   const float* __restrict__ mp_b1,
                     const float* __restrict__ mp_w2,   const float* __restrict__ mp_b2,
                     const float* __restrict__ bp_w1,   const float* __restrict__ bp_b1,
                     const float* __restrict__ bp_w2,   const float* __restrict__ bp_b2,
                     const float* __restrict__ att_wq,  const float* __restrict__ att_bq,
                     const float* __restrict__ att_wa,  const float* __restrict__ att_ba,
                     const float* __restrict__ att_v,
                     const float* __restrict__ scale_w, const float* __restrict__ scale_b,
                     const float* __restrict__ out_w,   const float* __restrict__ out_b,
                     float* __restrict__ out, int want_attn)
{
    const int tid = blockIdx.x * BLK + threadIdx.x;
    extern __shared__ __align__(16) float smem[];
    float* s_x    = smem;                 // [SXF]
    float* s_aux  = smem + SXF;
    float* s_pq   = s_aux;                // [256]  (P2)
    float* s_sc   = s_aux + 256;          // [128]  (P2)
    float* s_red  = s_aux + 384;          // [8]    (P2)
    float* s_cx   = s_aux + 392;          // [768]  (P2)
    float* s_p3   = s_aux;                // [768]  (P3)
    float* s_part = s_aux;                // [6144] (P4)

    // ===================== PC1 =====================
    for (long i = tid; i < (long)BSZ*U1P; i += NTH){
        int k = (int)(i / U1P), n = (int)(i - (long)k*U1P);
        g_w1pad[i] = (n < U1N) ? bp_w1[(long)k*U1N + n] : 0.f;
    }
    for (int i = tid; i < BB*BLEN*BDIM; i += NTH){
        int b = i / (BLEN*BDIM), r = i - b*(BLEN*BDIM);
        g_hist[((long)b*HLEN + TDEC)*BDIM + r] = 0.f;
    }
    for (int i = tid; i < BB*16*HID; i += NTH){
        int b = i / (16*HID), r = i - b*(16*HID);
        g_hhr[((long)b*HHL + 116)*HID + r] = 0.f;
    }
    for (int i = tid; i < BB*TENC*(HID/8); i += NTH){
        int row = i >> 5, h0 = (i & 31) << 3;
        u64 a[4]; bias8(a, att_ba + h0);
        dot8(inputs + (long)row*INDIM, att_wa + h0, HID, INDIM, a);
        store8(g_pa + (long)row*HID + h0, a);
    }
    for (int i = tid; i < TDEC*BB*5; i += NTH){
        int row = i / 5, n0 = (i - row*5) << 3;
        int tt = row >> 4, b = row & 15;
        u64 a[4]; bias8(a, mp_b1 + n0);
        if (tt > 0) dot8(targets + ((long)b*TDEC + (tt-1))*OUTD, mp_w1 + n0, MH1, OUTD, a);
        float v[8]; unp8(a, v);
        #pragma unroll
        for (int j = 0; j < 8; j++) g_mh[(long)row*MH1 + n0 + j] = fmaxf(v[j], 0.f);
    }
    for (int i = tid; i < U1N*HID; i += NTH){
        int j = i >> 8, h = i & 255;
        const float4* x = reinterpret_cast<const float4*>(bp_w2 + (long)j*BDIM);
        const float4* w = reinterpret_cast<const float4*>(scale_w + (long)h*BDIM);
        float acc = 0.f;
        #pragma unroll 4
        for (int k = 0; k < BDIM/4; k++){
            float4 xa = x[k], wa = w[k];
            acc += xa.x*wa.x + xa.y*wa.y + xa.z*wa.z + xa.w*wa.w;
        }
        g_W2S[(long)j*HID + h] = acc;
    }
    for (int h = tid; h < HID; h += NTH){
        const float* w = scale_w + (long)h*BDIM;
        float acc = 0.f;
        for (int k = 0; k < BDIM; k++) acc += bp_b2[k]*w[k];
        g_b2s[h] = acc;
    }
    // cst staging: 16 row-slices of 272 (stored in g_outp rows 0..15)
    for (int i = tid; i < 16*50; i += NTH){
        int p = i / 50, o0 = (i - p*50) << 3;
        u64 a[4]; zero8(a);
        const float* W = out_w + (long)(p*272)*OUTD + o0;
        for (int k = 0; k < 272; k++){
            u64 xx = pk1(scale_b[(p*272 + k) & 255]);
            ulonglong2 wA = *reinterpret_cast<const ulonglong2*>(W);
            ulonglong2 wB = *reinterpret_cast<const ulonglong2*>(W + 4);
            W += OUTD;
            fma2(a[0],xx,wA.x); fma2(a[1],xx,wA.y); fma2(a[2],xx,wB.x); fma2(a[3],xx,wB.y);
        }
        store8(g_outp + (long)p*OUTD + o0, a);
    }
    gsync();

    // ===================== PC2 =====================
    for (int i = tid; i < TDEC*BB*10; i += NTH){
        int row = i / 10, n0 = (i - row*10) << 3;
        u64 a[4]; bias8(a, mp_b2 + n0);
        dot8(g_mh + (long)row*MH1, mp_w2 + n0, MEMD, MH1, a);
        store8(g_memp + (long)row*MEMD + n0, a);
    }
    for (int i = tid; i < U1N*50; i += NTH){
        int j = i / 50, o0 = (i - j*50) << 3;
        u64 a[4]; zero8(a);
        dot8(g_W2S + (long)j*HID, out_w + o0, OUTD, HID, a);
        store8(g_W0 + (long)j*OUTD + o0, a);
    }
    for (int o = tid; o < OUTD; o += NTH){
        float v = out_b[o];
        for (int p = 0; p < 16; p++) v += g_outp[(long)p*OUTD + o];
        for (int h = 0; h < HID; h++) v += g_b2s[h] * out_w[(long)h*OUTD + o];
        g_cst[o] = v;
    }
    gsync();

    // ===================== decode loop =====================
    for (int t = 0; t < TDEC; t++){
        const int hbase = TDEC - t;

        // ---- P1: big GEMM partials (422 tiles over 148 CTAs x 3 groups) ----
        {
            const int g  = threadIdx.x >> 8;           // 0..2
            const int q  = threadIdx.x & 255;
            const int tj = q >> 4, b = q & 15;
            const int tau = g*GRID + blockIdx.x;
            int kind = -1, cb2 = 0, p = 0;
            if (tau < 210){ kind = 0; cb2 = tau/S1; p = tau - cb2*S1; }
            else if (tau < 294){ int ix = tau-210; kind = 1; cb2 = ix/S2; p = ix - cb2*S2; }
            else if (tau < NTILE){ int ix = tau-294; kind = 2; cb2 = ix/S3; p = ix - cb2*S3; }
            float* sxg = s_x + g*GST;
            if (kind == 0){
                int k0 = p*C1;
                #pragma unroll
                for (int bb = 0; bb < 16; bb++)
                    if (q < C1) sxg[bb*137 + q] = __ldcg(&g_hist[(long)(bb*HLEN + hbase)*BDIM + k0 + q]);
            } else if (kind == 1){
                int k0 = p*C2;
                #pragma unroll
                for (int bb = 0; bb < 16; bb++)
                    if (q < C2) sxg[bb*137 + q] = __ldcg(&g_hist[(long)(bb*HLEN + hbase)*BDIM + k0 + q]);
            } else if (kind == 2){
                int k0 = p*C3;
                #pragma unroll
                for (int bb = 0; bb < 16; bb++)
                    if (q < C3) sxg[bb*137 + q] = __ldcg(&g_hhr[(long)(bb*HHL + (116 - t))*HID + k0 + q]);
            }
            __syncthreads();
            if (kind == 0){
                int j0 = cb2*128 + tj*8, k0 = p*C1;
                if (j0 < U1P){
                    u64 a[4]; zero8(a);
                    dot8(sxg + b*137, g_w1pad + (long)(BDIM + k0)*U1P + j0, U1P, C1, a);
                    store8(g_u1p + (long)(p*BB + b)*U1P + j0, a);
                }
            } else if (kind == 1){
                int h0 = cb2*128 + tj*8, k0 = p*C2;
                u64 a[4]; zero8(a);
                dot8(sxg + b*137, att_wq + (long)k0*HID + h0, HID, C2, a);
                store8(g_pqp + (long)(p*BB + b)*HID + h0, a);
            } else if (kind == 2){
                int o0 = cb2*128 + tj*8, k0 = p*C3;
                if (o0 < OUTD){
                    u64 a[4]; zero8(a);
                    dot8(sxg + b*137, out_w + (long)(HID + k0)*OUTD + o0, OUTD, C3, a);
                    store8(g_outp + (long)(p*BB + b)*OUTD + o0, a);
                }
            }
        }
        gsync();

        // ---- P2: attention (blocks 0..15, 768 threads each) ----
        if (blockIdx.x < BB){
            const int b = blockIdx.x, i = threadIdx.x;
            if (i < HID){
                float v = att_bq[i];
                #pragma unroll 7
                for (int p = 0; p < NPQ; p++) v += __ldcg(&g_pqp[(long)(p*BB + b)*HID + i]);
                s_pq[i] = v;
            }
            __syncthreads();
            if (i < 512){
                int te = i >> 2, c = i & 3, h0 = c*64;
                const float* pa = g_pa + ((long)b*TENC + te)*HID + h0;
                const float* av = att_v + h0;
                float part = 0.f;
                #pragma unroll 8
                for (int h = 0; h < 64; h++)
                    part += ftanh(s_pq[h0 + h] + pa[h]) * av[h];
                part += __shfl_xor_sync(0xffffffffu, part, 1);
                part += __shfl_xor_sync(0xffffffffu, part, 2);
                if (c == 0) s_sc[te] = part;
            }
            __syncthreads();
            if (i < TENC){
                float x = s_sc[i];
                for (int o = 16; o > 0; o >>= 1) x = fmaxf(x, __shfl_xor_sync(~0u, x, o));
                if ((i & 31) == 0) s_red[i >> 5] = x;
            }
            __syncthreads();
            if (i < TENC){
                float m = fmaxf(fmaxf(s_red[0], s_red[1]), fmaxf(s_red[2], s_red[3]));
                float e = __expf(s_sc[i] - m);
                float x = e;
                for (int o = 16; o > 0; o >>= 1) x += __shfl_xor_sync(~0u, x, o);
                if ((i & 31) == 0) s_red[4 + (i >> 5)] = x;
                s_sc[i] = e;
            }
            __syncthreads();
            if (i < TENC){
                float ssum = s_red[4] + s_red[5] + s_red[6] + s_red[7];
                float aw = s_sc[i] / ssum;
                s_sc[i] = aw;
                if (want_attn)
                    out[OUTS_ELEMS + ((long)b*TDEC + t)*TENC + i] = aw;
            }
            __syncthreads();
            {   // ctx: 3-way k-split over 768 threads
                int c = i >> 8, d = i & 255;
                int kb = (c == 0) ? 0 : (c == 1 ? 43 : 86);
                int ke = (c == 2) ? TENC : kb + 43;
                float acc = 0.f;
                const float* ip = inputs + (long)b*TENC*INDIM + d;
                #pragma unroll 8
                for (int k = kb; k < ke; k++) acc += s_sc[k] * ip[(long)k*INDIM];
                s_cx[c*256 + d] = acc;
            }
            __syncthreads();
            if (i < 256)
                g_top[b*BDIM + i] = s_cx[i] + s_cx[256 + i] + s_cx[512 + i];
            else if (i >= 512 && i < 512 + MEMD)
                g_top[b*BDIM + INDIM + (i - 512)] = g_memp[((long)t*BB + b)*MEMD + (i - 512)];
        }
        gsync();

        // ---- P3: u1 finalize (36 CTAs; 3-way partial+k split) ----
        if (blockIdx.x < 36){
            for (int idx = threadIdx.x; idx < BB*BDIM; idx += BLK){
                int bb = idx / BDIM, kk = idx - bb*BDIM;
                s_x[bb*337 + kk] = __ldcg(&g_top[idx]);
            }
            __syncthreads();
            const int g = threadIdx.x >> 8, q = threadIdx.x & 255;
            const int tj = q >> 4, b = q & 15;
            const int j = blockIdx.x*16 + tj;
            const int jc = min(j, U1N - 1);
            float acc = (g == 2) ? bp_b1[jc] : 0.f;
            #pragma unroll 7
            for (int p = g*14; p < g*14 + 14; p++)
                acc += __ldcg(&g_u1p[(long)(p*BB + b)*U1P + j]);
            const float* xs = s_x + b*337 + g*112;
            const float* w = bp_w1 + (long)(g*112)*U1N + jc;
            #pragma unroll 8
            for (int k = 0; k < 112; k++) acc += xs[k] * w[(long)k*U1N];
            s_p3[g*256 + q] = acc;
            __syncthreads();
            if (g == 0){
                float v = s_p3[q] + s_p3[256 + q] + s_p3[512 + q];
                if (j < U1N) g_ru1[b*U1P + j] = fmaxf(v, 0.f);
            }
        }
        gsync();

        // ---- P4: u / hh / out from relu(u1) (62 CTAs, 24-warp k-split) ----
        if (blockIdx.x < 62){
            for (int idx = threadIdx.x; idx < BB*U1N; idx += BLK){
                int bb = idx / U1N, kk = idx - bb*U1N;
                s_x[bb*577 + kk] = __ldcg(&g_ru1[bb*U1P + kk]);
            }
            __syncthreads();
            const int w    = threadIdx.x >> 5;
            const int lane = threadIdx.x & 31;
            const int og2  = (lane >> 4) & 1;
            const int b    = lane & 15;
            const int k0   = w * 24;
            const int kl   = min(24, U1N - k0);
            const float* x = s_x + b*577 + k0;
            u64 a[4];
            if (blockIdx.x < 21){                           // u
                int c0 = blockIdx.x*16 + og2*8;
                if (w == 0) bias8(a, bp_b2 + c0); else zero8(a);
                dot8(x, bp_w2 + (long)k0*BDIM + c0, BDIM, kl, a);
            } else if (blockIdx.x < 37){                    // hh
                int c0 = (blockIdx.x - 21)*16 + og2*8;
                if (w == 0) bias8(a, g_b2s + c0); else zero8(a);
                dot8(x, g_W2S + (long)k0*HID + c0, HID, kl, a);
            } else {                                        // out finalize
                int c0 = (blockIdx.x - 37)*16 + og2*8;
                float s[8];
                float4 pA = __ldcg(reinterpret_cast<const float4*>(&g_outp[(long)(w*BB + b)*OUTD + c0]));
                float4 pB = __ldcg(reinterpret_cast<const float4*>(&g_outp[(long)(w*BB + b)*OUTD + c0 + 4]));
                s[0]=pA.x; s[1]=pA.y; s[2]=pA.z; s[3]=pA.w;
                s[4]=pB.x; s[5]=pB.y; s[6]=pB.z; s[7]=pB.w;
                if (w < 8){                                  // slices 24..31
                    float4 qA = __ldcg(reinterpret_cast<const float4*>(&g_outp[(long)((w+24)*BB + b)*OUTD + c0]));
                    float4 qB = __ldcg(reinterpret_cast<const float4*>(&g_outp[(long)((w+24)*BB + b)*OUTD + c0 + 4]));
                    s[0]+=qA.x; s[1]+=qA.y; s[2]+=qA.z; s[3]+=qA.w;
                    s[4]+=qB.x; s[5]+=qB.y; s[6]+=qB.z; s[7]+=qB.w;
                }
                if (w == 0){
                    #pragma unroll
                    for (int i2 = 0; i2 < 8; i2++) s[i2] += g_cst[c0 + i2];
                }
                a[0]=pkab(s[0],s[1]); a[1]=pkab(s[2],s[3]);
                a[2]=pkab(s[4],s[5]); a[3]=pkab(s[6],s[7]);
                dot8(x, g_W0 + (long)k0*OUTD + c0, OUTD, kl, a);
            }
            store8(&s_part[w*256 + (og2*16 + b)*8], a);
            __syncthreads();
            if (threadIdx.x < 256){
                int ii = threadIdx.x;
                float v = 0.f;
                #pragma unroll
                for (int ww = 0; ww < 24; ww++) v += s_part[ww*256 + ii];
                int b2 = (ii >> 3) & 15, og = ii >> 7, c = ii & 7;
                int col = ((blockIdx.x < 21) ? blockIdx.x*16
                         : (blockIdx.x < 37) ? (blockIdx.x-21)*16
                                             : (blockIdx.x-37)*16) + og*8 + c;
                if (blockIdx.x < 21)
                    g_hist[(long)(b2*HLEN + (TDEC-1 - t))*BDIM + col] = v;
                else if (blockIdx.x < 37)
                    g_hhr[(long)(b2*HHL + (115 - t))*HID + col] = v;
                else
                    out[((long)b2*TDEC + t)*OUTD + col] = v;
            }
        }
        gsync();
    }
}

extern "C" void kernel_launch(void* const* d_in, const int* in_sizes, int n_in,
                              void* d_out, int out_size) {
    (void)in_sizes; (void)n_in;
    int want_attn = (out_size >= OUTS_ELEMS + ATT_ELEMS) ? 1 : 0;
    cudaFuncSetAttribute(decoder_persist,
                         cudaFuncAttributeMaxDynamicSharedMemorySize,
                         SMEM_FLOATS * (int)sizeof(float));
    decoder_persist<<<GRID, BLK, SMEM_FLOATS * sizeof(float)>>>(
        (const float*)d_in[0],  (const float*)d_in[1],
        (const float*)d_in[2],  (const float*)d_in[3],
        (const float*)d_in[4],  (const float*)d_in[5],
        (const float*)d_in[6],  (const float*)d_in[7],
        (const float*)d_in[8],  (const float*)d_in[9],
        (const float*)d_in[10], (const float*)d_in[11],
        (const float*)d_in[12], (const float*)d_in[13],
        (const float*)d_in[14],
        (const float*)d_in[15], (const float*)d_in[16],
        (const float*)d_in[17], (const float*)d_in[18],
        (float*)d_out, want_attn);
}